// round 10
// baseline (speedup 1.0000x reference)
#include <cuda_runtime.h>

#define BB 4
#define CC 128
#define NN 4096
#define OC 256
#define KNN 10

typedef unsigned long long u64;

// Packed f32x2 helpers (sm_103a: SASS FFMA2, only reachable via PTX)
#define FMA_F32X2(d, a, b, c) \
    asm("fma.rn.f32x2 %0, %1, %2, %3;" : "=l"(d) : "l"(a), "l"(b), "l"(c))
#define PACK_F32X2(out, lo, hi) \
    asm("mov.b64 %0, {%1, %2};" : "=l"(out) : "f"(lo), "f"(hi))
#define UNPACK_F32X2(lo, hi, in) \
    asm("mov.b64 {%0, %1}, %2;" : "=f"(lo), "=f"(hi) : "l"(in))

// Scratch (device globals — no allocation in kernel_launch)
static __device__ u64   g_slots[(size_t)BB * NN * KNN];  // concurrent top-10 keys (1.3 MB)
static __device__ float g_xx[BB * NN];
static __device__ float g_xT[(size_t)BB * NN * CC];      // x transposed [b][n][c]
static __device__ float g_mT[(size_t)BB * NN * CC];      // neighbor mean [b][n][c]
static __device__ int   g_idx[BB * NN * KNN];
static __device__ float g_Wcat[OC * 2 * CC];

// ---------------------------------------------------------------------------
// key = (orderable(v) << 12) | (4095 - col): u64 order == (value desc, col asc)
__device__ __forceinline__ u64 score_key(float v, int col) {
    unsigned u = __float_as_uint(v);
    unsigned o = (u & 0x80000000u) ? ~u : (u | 0x80000000u);
    return ((u64)o << 12) | (u64)(4095 - col);
}
__device__ __forceinline__ float key_value(u64 key) {
    if (key == 0ull) return -3.4028235e38f;   // sentinel: empty slot
    unsigned o = (unsigned)(key >> 12);
    unsigned u = (o & 0x80000000u) ? (o ^ 0x80000000u) : ~o;
    return __uint_as_float(u);
}

// Exact concurrent top-10 insert.  Each step conserves the multiset; every
// dropped carry was <= each slot it passed (slots are monotone) => final
// slots hold the exact top-10 of all inserted keys, interleaving-independent.
__device__ __forceinline__ void cascade10(u64* s, u64 key) {
#pragma unroll
    for (int k = 0; k < KNN; k++) {
        u64 old = atomicMax(s + k, key);
        if (old < key) key = old;      // carry the displaced smaller key
        if (key == 0ull) return;       // hit an empty slot: done
    }
}

// ---------------------------------------------------------------------------
// K0: re-init slots each launch (graph replays!)
__global__ void zero_slots_kernel() {
    size_t i = (size_t)blockIdx.x * 256 + threadIdx.x;
    if (i < (size_t)BB * NN * KNN) g_slots[i] = 0ull;
}

// ---------------------------------------------------------------------------
// K1a: per-point squared norm  xx[b][n] = sum_c x[b][c][n]^2
__global__ void xx_kernel(const float* __restrict__ x) {
    int b = blockIdx.y;
    int n = blockIdx.x * blockDim.x + threadIdx.x;
    const float* xb = x + (size_t)b * CC * NN;
    float s = 0.f;
#pragma unroll 8
    for (int c = 0; c < CC; c++) {
        float v = xb[(size_t)c * NN + n];
        s += v * v;
    }
    g_xx[b * NN + n] = s;
}

// ---------------------------------------------------------------------------
// K1b: transpose x[b][c][n] -> xT[b][n][c]
__global__ void transpose_kernel(const float* __restrict__ x) {
    __shared__ float tile[32][33];
    int b  = blockIdx.z;
    int c0 = blockIdx.y * 32;
    int n0 = blockIdx.x * 32;
    const float* xb = x + (size_t)b * CC * NN;
    int tx = threadIdx.x, ty = threadIdx.y;  // (32, 8)
#pragma unroll
    for (int r = 0; r < 32; r += 8)
        tile[ty + r][tx] = xb[(size_t)(c0 + ty + r) * NN + n0 + tx];
    __syncthreads();
#pragma unroll
    for (int r = 0; r < 32; r += 8)
        g_xT[((size_t)b * NN + n0 + ty + r) * CC + c0 + tx] = tile[tx][ty + r];
}

// ---------------------------------------------------------------------------
// Shared 8x8-per-thread FFMA2 micro-kernel step
#define MICRO_FFMA2(ab, bb_)                                                 \
    do {                                                                     \
        float4 a0 = *(const float4*)((ab) + ty * 8);                         \
        float4 a1 = *(const float4*)((ab) + ty * 8 + 4);                     \
        float4 b0 = *(const float4*)((bb_) + tx * 8);                        \
        float4 b1 = *(const float4*)((bb_) + tx * 8 + 4);                    \
        u64 aa[8], bbp[4];                                                   \
        PACK_F32X2(aa[0], a0.x, a0.x); PACK_F32X2(aa[1], a0.y, a0.y);        \
        PACK_F32X2(aa[2], a0.z, a0.z); PACK_F32X2(aa[3], a0.w, a0.w);        \
        PACK_F32X2(aa[4], a1.x, a1.x); PACK_F32X2(aa[5], a1.y, a1.y);        \
        PACK_F32X2(aa[6], a1.z, a1.z); PACK_F32X2(aa[7], a1.w, a1.w);        \
        PACK_F32X2(bbp[0], b0.x, b0.y); PACK_F32X2(bbp[1], b0.z, b0.w);      \
        PACK_F32X2(bbp[2], b1.x, b1.y); PACK_F32X2(bbp[3], b1.z, b1.w);      \
        _Pragma("unroll")                                                    \
        for (int i = 0; i < 8; i++)                                          \
            _Pragma("unroll")                                                \
            for (int p = 0; p < 4; p++)                                      \
                FMA_F32X2(acc2[i][p], aa[i], bbp[p], acc2[i][p]);            \
    } while (0)

// ---------------------------------------------------------------------------
// K2: symmetric Gram; epilogue feeds scores straight into the atomic top-10.
// No score matrix, no smem stage, no per-thread lists.
__global__ void __launch_bounds__(256) gram_kernel(const float* __restrict__ x) {
    __shared__ float As[2][1024];
    __shared__ float Bs[2][1024];

    int b = blockIdx.y;
    int t = blockIdx.x;
    int ti = 0;
    while ((ti + 1) * 32 - (ti + 1) * ti / 2 <= t) ti++;
    int tj = ti + (t - (ti * 32 - ti * (ti - 1) / 2));
    int n0 = ti * 128, m0 = tj * 128;

    const float* xb = x + (size_t)b * CC * NN;
    int tid = threadIdx.x;
    int tx = tid % 16, ty = tid / 16;

    u64 acc2[8][4];
#pragma unroll
    for (int i = 0; i < 8; i++)
#pragma unroll
        for (int p = 0; p < 4; p++) acc2[i][p] = 0ull;

#pragma unroll
    for (int l = 0; l < 4; l++) {
        int e = tid + l * 256;
        int kk = e >> 7, col = e & 127;
        As[0][e] = xb[(size_t)kk * NN + n0 + col];
        Bs[0][e] = xb[(size_t)kk * NN + m0 + col];
    }
    __syncthreads();

    int buf = 0;
    for (int c0 = 0; c0 < CC; c0 += 8) {
        int nc = c0 + 8;
        float ra[4], rb[4];
        if (nc < CC) {
#pragma unroll
            for (int l = 0; l < 4; l++) {
                int e = tid + l * 256;
                int kk = e >> 7, col = e & 127;
                ra[l] = xb[(size_t)(nc + kk) * NN + n0 + col];
                rb[l] = xb[(size_t)(nc + kk) * NN + m0 + col];
            }
        }
#pragma unroll
        for (int kk = 0; kk < 8; kk++) {
            MICRO_FFMA2(&As[buf][kk * 128], &Bs[buf][kk * 128]);
        }
        if (nc < CC) {
            int ob = buf ^ 1;
#pragma unroll
            for (int l = 0; l < 4; l++) {
                int e = tid + l * 256;
                As[ob][e] = ra[l];
                Bs[ob][e] = rb[l];
            }
            __syncthreads();
            buf = ob;
        }
    }

    // unpack accumulators
    float acc[8][8];
#pragma unroll
    for (int i = 0; i < 8; i++)
#pragma unroll
        for (int p = 0; p < 4; p++)
            UNPACK_F32X2(acc[i][2 * p], acc[i][2 * p + 1], acc2[i][p]);

    float xxm[8], xxn[8];
#pragma unroll
    for (int j = 0; j < 8; j++) xxm[j] = g_xx[b * NN + m0 + tx * 8 + j];
#pragma unroll
    for (int i = 0; i < 8; i++) xxn[i] = g_xx[b * NN + n0 + ty * 8 + i];

    // ---- direct tile: rows n0+ty*8+i, cols m0+tx*8+j ----
#pragma unroll
    for (int i = 0; i < 8; i++) {
        int row = n0 + ty * 8 + i;
        u64* sl = g_slots + ((size_t)b * NN + row) * KNN;
        float thr = key_value(__ldcg(sl + 9));
        // phase 1: cascade this thread's row-max first (storm damper)
        float vmax = -3.4028235e38f; int jm = 0;
#pragma unroll
        for (int j = 0; j < 8; j++) {
            float v = 2.f * acc[i][j] - xxm[j];
            if (v > vmax) { vmax = v; jm = j; }
        }
        if (vmax >= thr) {
            cascade10(sl, score_key(vmax, m0 + tx * 8 + jm));
            thr = key_value(__ldcg(sl + 9));
        }
        // phase 2: remaining elements under the refreshed threshold
#pragma unroll
        for (int j = 0; j < 8; j++) {
            if (j == jm) continue;
            float v = 2.f * acc[i][j] - xxm[j];
            if (v >= thr) cascade10(sl, score_key(v, m0 + tx * 8 + j));
        }
    }

    // ---- mirror tile: rows m0+tx*8+j, cols n0+ty*8+i ----
    if (ti != tj) {
#pragma unroll
        for (int j = 0; j < 8; j++) {
            int row = m0 + tx * 8 + j;
            u64* sl = g_slots + ((size_t)b * NN + row) * KNN;
            float thr = key_value(__ldcg(sl + 9));
            float vmax = -3.4028235e38f; int im = 0;
#pragma unroll
            for (int i = 0; i < 8; i++) {
                float v = 2.f * acc[i][j] - xxn[i];
                if (v > vmax) { vmax = v; im = i; }
            }
            if (vmax >= thr) {
                cascade10(sl, score_key(vmax, n0 + ty * 8 + im));
                thr = key_value(__ldcg(sl + 9));
            }
#pragma unroll
            for (int i = 0; i < 8; i++) {
                if (i == im) continue;
                float v = 2.f * acc[i][j] - xxn[i];
                if (v >= thr) cascade10(sl, score_key(v, n0 + ty * 8 + i));
            }
        }
    }
}

// ---------------------------------------------------------------------------
// K3: decode slots -> sorted indices (key order == jax order; keys unique)
__global__ void __launch_bounds__(256) decode_topk_kernel() {
    const unsigned FULL = 0xffffffffu;
    int gw   = (blockIdx.x * 256 + threadIdx.x) >> 5;  // row
    int lane = threadIdx.x & 31;
    u64 key = 0ull;
    if (lane < KNN) key = g_slots[(size_t)gw * KNN + lane];
    int rank = 0;
#pragma unroll
    for (int j = 0; j < KNN; j++) {
        u64 other = __shfl_sync(FULL, key, j);
        if (other > key) rank++;
    }
    if (lane < KNN) g_idx[gw * KNN + rank] = 4095 - (int)(key & 0xFFFull);
}

// ---------------------------------------------------------------------------
// K4: neighbor mean  mT[b][n][c] = (1/K) sum_k xT[b][idx_k][c]
__global__ void gather_kernel() {
    int b = blockIdx.y;
    int n = blockIdx.x;
    int c = threadIdx.x;  // 128
    __shared__ int sidx[KNN];
    if (c < KNN) sidx[c] = g_idx[(b * NN + n) * KNN + c];
    __syncthreads();
    float acc = 0.f;
#pragma unroll
    for (int k = 0; k < KNN; k++)
        acc += g_xT[((size_t)b * NN + sidx[k]) * CC + c];
    g_mT[((size_t)b * NN + n) * CC + c] = acc / (float)KNN;
}

// ---------------------------------------------------------------------------
// K5: Wcat[o][c] = W1 for c<128, (W2 - W1) for c>=128
__global__ void wcat_kernel(const float* __restrict__ W) {
    int idx = blockIdx.x * 256 + threadIdx.x;
    int c = idx % (2 * CC);
    float v = W[idx];
    if (c >= CC) v -= W[idx - CC];
    g_Wcat[idx] = v;
}

// ---------------------------------------------------------------------------
// K6: out[b][o][n] = sum_c Wcat[o][c] * cat[c][n] + bias[o], FFMA2 mainloop.
__global__ void __launch_bounds__(256) out_gemm_kernel(
    const float* __restrict__ x, const float* __restrict__ bias,
    float* __restrict__ out) {
    __shared__ float As[2][1024];
    __shared__ float Bs[2][1024];

    int b  = blockIdx.z;
    int o0 = blockIdx.y * 128;
    int n0 = blockIdx.x * 128;
    const float* xb = x + (size_t)b * CC * NN;

    int tid = threadIdx.x;
    int tx = tid % 16, ty = tid / 16;

    u64 acc2[8][4];
#pragma unroll
    for (int i = 0; i < 8; i++)
#pragma unroll
        for (int p = 0; p < 4; p++) acc2[i][p] = 0ull;

    {
        float ra[4], rb[4];
#pragma unroll
        for (int l = 0; l < 4; l++) {
            int e  = tid + l * 256;
            int kk = e % 8;
            int i  = e / 8;
            ra[l] = g_Wcat[(o0 + i) * (2 * CC) + kk];
            rb[l] = g_mT[((size_t)b * NN + n0 + i) * CC + kk];
        }
#pragma unroll
        for (int l = 0; l < 4; l++) {
            int e = tid + l * 256;
            As[0][(e % 8) * 128 + e / 8] = ra[l];
            Bs[0][(e % 8) * 128 + e / 8] = rb[l];
        }
        __syncthreads();
    }

    int buf = 0;
    for (int c0 = 0; c0 < 2 * CC; c0 += 8) {
        int nc = c0 + 8;
        float ra[4], rb[4];
        bool rb_xlayout = false;
        if (nc < 2 * CC) {
#pragma unroll
            for (int l = 0; l < 4; l++) {
                int e  = tid + l * 256;
                int kk = e % 8;
                int i  = e / 8;
                ra[l] = g_Wcat[(o0 + i) * (2 * CC) + nc + kk];
            }
            if (nc < CC) {
#pragma unroll
                for (int l = 0; l < 4; l++) {
                    int e  = tid + l * 256;
                    int kk = e % 8;
                    int j  = e / 8;
                    rb[l] = g_mT[((size_t)b * NN + n0 + j) * CC + nc + kk];
                }
            } else {
                rb_xlayout = true;
#pragma unroll
                for (int l = 0; l < 4; l++) {
                    int e  = tid + l * 256;
                    int kk = e / 128;
                    int j  = e % 128;
                    rb[l] = xb[(size_t)(nc - CC + kk) * NN + n0 + j];
                }
            }
        }
#pragma unroll
        for (int kk = 0; kk < 8; kk++) {
            MICRO_FFMA2(&As[buf][kk * 128], &Bs[buf][kk * 128]);
        }
        if (nc < 2 * CC) {
            int ob = buf ^ 1;
#pragma unroll
            for (int l = 0; l < 4; l++) {
                int e = tid + l * 256;
                As[ob][(e % 8) * 128 + e / 8] = ra[l];
            }
            if (!rb_xlayout) {
#pragma unroll
                for (int l = 0; l < 4; l++) {
                    int e = tid + l * 256;
                    Bs[ob][(e % 8) * 128 + e / 8] = rb[l];
                }
            } else {
#pragma unroll
                for (int l = 0; l < 4; l++) {
                    int e = tid + l * 256;
                    Bs[ob][(e / 128) * 128 + (e % 128)] = rb[l];
                }
            }
            __syncthreads();
            buf = ob;
        }
    }

    float acc[8][8];
#pragma unroll
    for (int i = 0; i < 8; i++)
#pragma unroll
        for (int p = 0; p < 4; p++)
            UNPACK_F32X2(acc[i][2 * p], acc[i][2 * p + 1], acc2[i][p]);

#pragma unroll
    for (int i = 0; i < 8; i++) {
        int o = o0 + ty * 8 + i;
        float bv = bias[o];
        float* orow = out + ((size_t)(b * OC + o)) * NN + n0 + tx * 8;
        float v[8];
#pragma unroll
        for (int j = 0; j < 8; j++) v[j] = acc[i][j] + bv;
        ((float4*)orow)[0] = make_float4(v[0], v[1], v[2], v[3]);
        ((float4*)orow)[1] = make_float4(v[4], v[5], v[6], v[7]);
    }
}

// ---------------------------------------------------------------------------
extern "C" void kernel_launch(void* const* d_in, const int* in_sizes, int n_in,
                              void* d_out, int out_size) {
    const float* x    = (const float*)d_in[0];
    const float* W    = (const float*)d_in[1];
    const float* bias = (const float*)d_in[2];
    float* out = (float*)d_out;

    zero_slots_kernel<<<(BB * NN * KNN + 255) / 256, 256>>>();
    xx_kernel<<<dim3(NN / 256, BB), 256>>>(x);
    transpose_kernel<<<dim3(NN / 32, CC / 32, BB), dim3(32, 8)>>>(x);
    gram_kernel<<<dim3(528, BB), 256>>>(x);
    decode_topk_kernel<<<dim3(BB * NN / 8), 256>>>();
    gather_kernel<<<dim3(NN, BB), 128>>>();
    wcat_kernel<<<OC, 256>>>(W);
    out_gemm_kernel<<<dim3(NN / 128, OC / 128, BB), 256>>>(x, bias, out);
}

// round 11
// speedup vs baseline: 2.8109x; 2.8109x over previous
#include <cuda_runtime.h>

#define BB 4
#define CC 128
#define NN 4096
#define OC 256
#define KNN 10

typedef unsigned long long u64;

// Packed f32x2 helpers (sm_103a: SASS FFMA2, only reachable via PTX)
#define FMA_F32X2(d, a, b, c) \
    asm("fma.rn.f32x2 %0, %1, %2, %3;" : "=l"(d) : "l"(a), "l"(b), "l"(c))
#define PACK_F32X2(out, lo, hi) \
    asm("mov.b64 %0, {%1, %2};" : "=l"(out) : "f"(lo), "f"(hi))
#define UNPACK_F32X2(lo, hi, in) \
    asm("mov.b64 {%0, %1}, %2;" : "=f"(lo), "=f"(hi) : "l"(in))

// Scratch (device globals — no allocation in kernel_launch)
static __device__ float g_score[(size_t)BB * NN * NN];   // 268 MB
static __device__ float g_xx[BB * NN];
static __device__ float g_xT[(size_t)BB * NN * CC];      // x transposed [b][n][c]
static __device__ float g_mT[(size_t)BB * NN * CC];      // neighbor mean [b][n][c]
static __device__ int   g_idx[BB * NN * KNN];
static __device__ float g_Wcat[OC * 2 * CC];

// ---------------------------------------------------------------------------
// K1a: per-point squared norm  xx[b][n] = sum_c x[b][c][n]^2
__global__ void xx_kernel(const float* __restrict__ x) {
    int b = blockIdx.y;
    int n = blockIdx.x * blockDim.x + threadIdx.x;
    const float* xb = x + (size_t)b * CC * NN;
    float s = 0.f;
#pragma unroll 8
    for (int c = 0; c < CC; c++) {
        float v = xb[(size_t)c * NN + n];
        s += v * v;
    }
    g_xx[b * NN + n] = s;
}

// ---------------------------------------------------------------------------
// K1b: transpose x[b][c][n] -> xT[b][n][c]
__global__ void transpose_kernel(const float* __restrict__ x) {
    __shared__ float tile[32][33];
    int b  = blockIdx.z;
    int c0 = blockIdx.y * 32;
    int n0 = blockIdx.x * 32;
    const float* xb = x + (size_t)b * CC * NN;
    int tx = threadIdx.x, ty = threadIdx.y;  // (32, 8)
#pragma unroll
    for (int r = 0; r < 32; r += 8)
        tile[ty + r][tx] = xb[(size_t)(c0 + ty + r) * NN + n0 + tx];
    __syncthreads();
#pragma unroll
    for (int r = 0; r < 32; r += 8)
        g_xT[((size_t)b * NN + n0 + ty + r) * CC + c0 + tx] = tile[tx][ty + r];
}

// ---------------------------------------------------------------------------
// Shared 8x8-per-thread FFMA2 micro-kernel step
#define MICRO_FFMA2(ab, bb_)                                                 \
    do {                                                                     \
        float4 a0 = *(const float4*)((ab) + ty * 8);                         \
        float4 a1 = *(const float4*)((ab) + ty * 8 + 4);                     \
        float4 b0 = *(const float4*)((bb_) + tx * 8);                        \
        float4 b1 = *(const float4*)((bb_) + tx * 8 + 4);                    \
        u64 aa[8], bbp[4];                                                   \
        PACK_F32X2(aa[0], a0.x, a0.x); PACK_F32X2(aa[1], a0.y, a0.y);        \
        PACK_F32X2(aa[2], a0.z, a0.z); PACK_F32X2(aa[3], a0.w, a0.w);        \
        PACK_F32X2(aa[4], a1.x, a1.x); PACK_F32X2(aa[5], a1.y, a1.y);        \
        PACK_F32X2(aa[6], a1.z, a1.z); PACK_F32X2(aa[7], a1.w, a1.w);        \
        PACK_F32X2(bbp[0], b0.x, b0.y); PACK_F32X2(bbp[1], b0.z, b0.w);      \
        PACK_F32X2(bbp[2], b1.x, b1.y); PACK_F32X2(bbp[3], b1.z, b1.w);      \
        _Pragma("unroll")                                                    \
        for (int i = 0; i < 8; i++)                                          \
            _Pragma("unroll")                                                \
            for (int p = 0; p < 4; p++)                                      \
                FMA_F32X2(acc2[i][p], aa[i], bbp[p], acc2[i][p]);            \
    } while (0)

// ---------------------------------------------------------------------------
// K2: symmetric Gram + score epilogue (R8 version — known good).
#define GRAM_SMEM_BYTES (128 * 129 * 4)

__global__ void __launch_bounds__(256) gram_kernel(const float* __restrict__ x) {
    extern __shared__ float sm[];
    float* As = sm;              // [2][8][128]
    float* Bs = sm + 2 * 8 * 128;
    float* stage = sm;           // [128][129], reused after compute

    int b = blockIdx.y;
    int t = blockIdx.x;
    int ti = 0;
    while ((ti + 1) * 32 - (ti + 1) * ti / 2 <= t) ti++;
    int tj = ti + (t - (ti * 32 - ti * (ti - 1) / 2));
    int n0 = ti * 128, m0 = tj * 128;

    const float* xb = x + (size_t)b * CC * NN;
    int tid = threadIdx.x;
    int tx = tid % 16, ty = tid / 16;

    u64 acc2[8][4];
#pragma unroll
    for (int i = 0; i < 8; i++)
#pragma unroll
        for (int p = 0; p < 4; p++) acc2[i][p] = 0ull;

#pragma unroll
    for (int l = 0; l < 4; l++) {
        int e = tid + l * 256;
        int kk = e >> 7, col = e & 127;
        As[e] = xb[(size_t)kk * NN + n0 + col];
        Bs[e] = xb[(size_t)kk * NN + m0 + col];
    }
    __syncthreads();

    int buf = 0;
    for (int c0 = 0; c0 < CC; c0 += 8) {
        int nc = c0 + 8;
        float ra[4], rb[4];
        if (nc < CC) {
#pragma unroll
            for (int l = 0; l < 4; l++) {
                int e = tid + l * 256;
                int kk = e >> 7, col = e & 127;
                ra[l] = xb[(size_t)(nc + kk) * NN + n0 + col];
                rb[l] = xb[(size_t)(nc + kk) * NN + m0 + col];
            }
        }
#pragma unroll
        for (int kk = 0; kk < 8; kk++) {
            MICRO_FFMA2(As + buf * 1024 + kk * 128, Bs + buf * 1024 + kk * 128);
        }
        if (nc < CC) {
            int ob = buf ^ 1;
#pragma unroll
            for (int l = 0; l < 4; l++) {
                int e = tid + l * 256;
                As[ob * 1024 + e] = ra[l];
                Bs[ob * 1024 + e] = rb[l];
            }
            __syncthreads();
            buf = ob;
        }
    }

    // unpack accumulators
    float acc[8][8];
#pragma unroll
    for (int i = 0; i < 8; i++)
#pragma unroll
        for (int p = 0; p < 4; p++)
            UNPACK_F32X2(acc[i][2 * p], acc[i][2 * p + 1], acc2[i][p]);

    float xxm[8];
#pragma unroll
    for (int j = 0; j < 8; j++) xxm[j] = g_xx[b * NN + m0 + tx * 8 + j];
#pragma unroll
    for (int i = 0; i < 8; i++) {
        int n = n0 + ty * 8 + i;
        float v[8];
#pragma unroll
        for (int j = 0; j < 8; j++) v[j] = 2.f * acc[i][j] - xxm[j];
        float* row = g_score + ((size_t)b * NN + n) * NN + m0 + tx * 8;
        ((float4*)row)[0] = make_float4(v[0], v[1], v[2], v[3]);
        ((float4*)row)[1] = make_float4(v[4], v[5], v[6], v[7]);
    }

    if (ti != tj) {
        __syncthreads();
        float xxn[8];
#pragma unroll
        for (int i = 0; i < 8; i++) xxn[i] = g_xx[b * NN + n0 + ty * 8 + i];
#pragma unroll
        for (int i = 0; i < 8; i++)
#pragma unroll
            for (int j = 0; j < 8; j++)
                stage[(tx * 8 + j) * 129 + ty * 8 + i] = 2.f * acc[i][j] - xxn[i];
        __syncthreads();
        int r  = tid >> 1;
        int ch = (tid & 1) * 64;
        float* row = g_score + ((size_t)b * NN + m0 + r) * NN + n0 + ch;
        const float* srow = stage + r * 129 + ch;
#pragma unroll
        for (int q = 0; q < 16; q++) {
            ((float4*)row)[q] = make_float4(srow[q * 4 + 0], srow[q * 4 + 1],
                                            srow[q * 4 + 2], srow[q * 4 + 3]);
        }
    }
}

// ---------------------------------------------------------------------------
// K3: top-K per row, one warp per row.  R5 scheme + warm start:
// Chunk 0 (first 128 elems) is handled by PRIVATE per-lane insertion
// (4 elems each, no ballots) followed by one exact 10-round shuffle merge
// whose broadcast winners rebuild the replicated top-10 in all lanes.
// Main loop (chunks 1..31) = R5 replicated-list scheme with warm threshold:
// ~35 steady-state admissions instead of ~160 with a cold threshold.
// Tie-breaks everywhere: value desc, index asc (matches jax.lax.top_k).
__global__ void __launch_bounds__(256) topk_kernel() {
    const unsigned FULL = 0xffffffffu;
    int gw   = (blockIdx.x * 256 + threadIdx.x) >> 5;  // global row
    int lane = threadIdx.x & 31;
    int b = gw >> 12;        // / NN
    int n = gw & (NN - 1);
    const float4* row = (const float4*)(g_score + ((size_t)b * NN + n) * NN);

    const float NEG = -3.4028235e38f;
    float lv[KNN];
    int   li[KNN];

    // ---- warm start: private insert of chunk 0, then exact warp merge ----
    {
        float pv[KNN];
        int   pi[KNN];
#pragma unroll
        for (int k = 0; k < KNN; k++) { pv[k] = NEG; pi[k] = 0x7fffffff; }
        float4 c0 = row[lane];
        int base0 = lane * 4;
#pragma unroll
        for (int e = 0; e < 4; e++) {
            float v = (e == 0) ? c0.x : (e == 1) ? c0.y : (e == 2) ? c0.z : c0.w;
            int  ix = base0 + e;
            float cv = v; int ci = ix;
#pragma unroll
            for (int k = 0; k < KNN; k++) {
                bool sw = (cv > pv[k]) || (cv == pv[k] && ci < pi[k]);
                float tv = sw ? pv[k] : cv;
                int   tq = sw ? pi[k] : ci;
                pv[k] = sw ? cv : pv[k];
                pi[k] = sw ? ci : pi[k];
                cv = tv; ci = tq;
            }
        }
        // 10-round merge; winners broadcast -> replicated list in all lanes
#pragma unroll
        for (int r = 0; r < KNN; r++) {
            float cv = pv[0]; int ci = pi[0];
            float bv = cv;    int bi = ci;
#pragma unroll
            for (int off = 16; off; off >>= 1) {
                float ov = __shfl_xor_sync(FULL, bv, off);
                int   oi = __shfl_xor_sync(FULL, bi, off);
                if (ov > bv || (ov == bv && oi < bi)) { bv = ov; bi = oi; }
            }
            lv[r] = bv; li[r] = bi;
            if (bi == ci) {  // this lane won (indices unique): pop head
#pragma unroll
                for (int k = 0; k < KNN - 1; k++) { pv[k] = pv[k + 1]; pi[k] = pi[k + 1]; }
                pv[KNN - 1] = NEG; pi[KNN - 1] = 0x7fffffff;
            }
        }
    }
    float thr = lv[KNN - 1];
    int   tix = li[KNN - 1];

    // ---- main loop: chunks 1..31, replicated-list admissions ----
    float4 cur = row[32 + lane];
    for (int j = 1; j < NN / 4 / 32; j++) {
        float4 nxt;
        if (j < NN / 4 / 32 - 1) nxt = row[(j + 1) * 32 + lane];
        int base = (j * 32 + lane) * 4;
        float m4 = fmaxf(fmaxf(cur.x, cur.y), fmaxf(cur.z, cur.w));
        if (__ballot_sync(FULL, m4 >= thr)) {
            float ev0 = cur.x, ev1 = cur.y, ev2 = cur.z, ev3 = cur.w;
#pragma unroll
            for (int e = 0; e < 4; e++) {
                float v = (e == 0) ? ev0 : (e == 1) ? ev1 : (e == 2) ? ev2 : ev3;
                int idx = base + e;
                bool cand = (v > thr) || (v == thr && idx < tix);
                unsigned m = __ballot_sync(FULL, cand);
                while (m) {
                    int src = __ffs(m) - 1;
                    float bv = __shfl_sync(FULL, v, src);
                    int   bi = __shfl_sync(FULL, idx, src);
                    // coherent insert into replicated sorted list
                    float cv = bv; int ci = bi;
#pragma unroll
                    for (int k = 0; k < KNN; k++) {
                        bool sw = (cv > lv[k]) || (cv == lv[k] && ci < li[k]);
                        float tv = sw ? lv[k] : cv;
                        int   tq = sw ? li[k] : ci;
                        lv[k] = sw ? cv : lv[k];
                        li[k] = sw ? ci : li[k];
                        cv = tv; ci = tq;
                    }
                    thr = lv[KNN - 1]; tix = li[KNN - 1];
                    if (lane == src) cand = false;
                    cand = cand && ((v > thr) || (v == thr && idx < tix));
                    m = __ballot_sync(FULL, cand);
                }
            }
        }
        cur = nxt;
    }

#pragma unroll
    for (int k = 0; k < KNN; k++)
        if (lane == k) g_idx[(b * NN + n) * KNN + k] = li[k];
}

// ---------------------------------------------------------------------------
// K4: neighbor mean  mT[b][n][c] = (1/K) sum_k xT[b][idx_k][c]
__global__ void gather_kernel() {
    int b = blockIdx.y;
    int n = blockIdx.x;
    int c = threadIdx.x;  // 128
    __shared__ int sidx[KNN];
    if (c < KNN) sidx[c] = g_idx[(b * NN + n) * KNN + c];
    __syncthreads();
    float acc = 0.f;
#pragma unroll
    for (int k = 0; k < KNN; k++)
        acc += g_xT[((size_t)b * NN + sidx[k]) * CC + c];
    g_mT[((size_t)b * NN + n) * CC + c] = acc / (float)KNN;
}

// ---------------------------------------------------------------------------
// K5: Wcat[o][c] = W1 for c<128, (W2 - W1) for c>=128
__global__ void wcat_kernel(const float* __restrict__ W) {
    int idx = blockIdx.x * 256 + threadIdx.x;
    int c = idx % (2 * CC);
    float v = W[idx];
    if (c >= CC) v -= W[idx - CC];
    g_Wcat[idx] = v;
}

// ---------------------------------------------------------------------------
// K6: out[b][o][n] = sum_c Wcat[o][c] * cat[c][n] + bias[o], FFMA2 mainloop.
__global__ void __launch_bounds__(256) out_gemm_kernel(
    const float* __restrict__ x, const float* __restrict__ bias,
    float* __restrict__ out) {
    __shared__ float As[2][1024];
    __shared__ float Bs[2][1024];

    int b  = blockIdx.z;
    int o0 = blockIdx.y * 128;
    int n0 = blockIdx.x * 128;
    const float* xb = x + (size_t)b * CC * NN;

    int tid = threadIdx.x;
    int tx = tid % 16, ty = tid / 16;

    u64 acc2[8][4];
#pragma unroll
    for (int i = 0; i < 8; i++)
#pragma unroll
        for (int p = 0; p < 4; p++) acc2[i][p] = 0ull;

    {
        float ra[4], rb[4];
#pragma unroll
        for (int l = 0; l < 4; l++) {
            int e  = tid + l * 256;
            int kk = e % 8;
            int i  = e / 8;
            ra[l] = g_Wcat[(o0 + i) * (2 * CC) + kk];
            rb[l] = g_mT[((size_t)b * NN + n0 + i) * CC + kk];
        }
#pragma unroll
        for (int l = 0; l < 4; l++) {
            int e = tid + l * 256;
            As[0][(e % 8) * 128 + e / 8] = ra[l];
            Bs[0][(e % 8) * 128 + e / 8] = rb[l];
        }
        __syncthreads();
    }

    int buf = 0;
    for (int c0 = 0; c0 < 2 * CC; c0 += 8) {
        int nc = c0 + 8;
        float ra[4], rb[4];
        bool rb_xlayout = false;
        if (nc < 2 * CC) {
#pragma unroll
            for (int l = 0; l < 4; l++) {
                int e  = tid + l * 256;
                int kk = e % 8;
                int i  = e / 8;
                ra[l] = g_Wcat[(o0 + i) * (2 * CC) + nc + kk];
            }
            if (nc < CC) {
#pragma unroll
                for (int l = 0; l < 4; l++) {
                    int e  = tid + l * 256;
                    int kk = e % 8;
                    int j  = e / 8;
                    rb[l] = g_mT[((size_t)b * NN + n0 + j) * CC + nc + kk];
                }
            } else {
                rb_xlayout = true;
#pragma unroll
                for (int l = 0; l < 4; l++) {
                    int e  = tid + l * 256;
                    int kk = e / 128;
                    int j  = e % 128;
                    rb[l] = xb[(size_t)(nc - CC + kk) * NN + n0 + j];
                }
            }
        }
#pragma unroll
        for (int kk = 0; kk < 8; kk++) {
            MICRO_FFMA2(&As[buf][kk * 128], &Bs[buf][kk * 128]);
        }
        if (nc < 2 * CC) {
            int ob = buf ^ 1;
#pragma unroll
            for (int l = 0; l < 4; l++) {
                int e = tid + l * 256;
                As[ob][(e % 8) * 128 + e / 8] = ra[l];
            }
            if (!rb_xlayout) {
#pragma unroll
                for (int l = 0; l < 4; l++) {
                    int e = tid + l * 256;
                    Bs[ob][(e % 8) * 128 + e / 8] = rb[l];
                }
            } else {
#pragma unroll
                for (int l = 0; l < 4; l++) {
                    int e = tid + l * 256;
                    Bs[ob][(e / 128) * 128 + (e % 128)] = rb[l];
                }
            }
            __syncthreads();
            buf = ob;
        }
    }

    float acc[8][8];
#pragma unroll
    for (int i = 0; i < 8; i++)
#pragma unroll
        for (int p = 0; p < 4; p++)
            UNPACK_F32X2(acc[i][2 * p], acc[i][2 * p + 1], acc2[i][p]);

#pragma unroll
    for (int i = 0; i < 8; i++) {
        int o = o0 + ty * 8 + i;
        float bv = bias[o];
        float* orow = out + ((size_t)(b * OC + o)) * NN + n0 + tx * 8;
        float v[8];
#pragma unroll
        for (int j = 0; j < 8; j++) v[j] = acc[i][j] + bv;
        ((float4*)orow)[0] = make_float4(v[0], v[1], v[2], v[3]);
        ((float4*)orow)[1] = make_float4(v[4], v[5], v[6], v[7]);
    }
}

// ---------------------------------------------------------------------------
extern "C" void kernel_launch(void* const* d_in, const int* in_sizes, int n_in,
                              void* d_out, int out_size) {
    const float* x    = (const float*)d_in[0];
    const float* W    = (const float*)d_in[1];
    const float* bias = (const float*)d_in[2];
    float* out = (float*)d_out;

    cudaFuncSetAttribute(gram_kernel,
                         cudaFuncAttributeMaxDynamicSharedMemorySize,
                         GRAM_SMEM_BYTES);

    xx_kernel<<<dim3(NN / 256, BB), 256>>>(x);
    transpose_kernel<<<dim3(NN / 32, CC / 32, BB), dim3(32, 8)>>>(x);
    gram_kernel<<<dim3(528, BB), 256, GRAM_SMEM_BYTES>>>(x);
    topk_kernel<<<dim3(BB * NN / 8), 256>>>();
    gather_kernel<<<dim3(NN, BB), 128>>>();
    wcat_kernel<<<OC, 256>>>(W);
    out_gemm_kernel<<<dim3(NN / 128, OC / 128, BB), 256>>>(x, bias, out);
}